// round 13
// baseline (speedup 1.0000x reference)
#include <cuda_runtime.h>
#include <cuda_bf16.h>
#include <math.h>

// ---------------- problem constants ----------------
#define NN   50000
#define EE   800000
#define EP   (EE + NN)      // 850000
#define HH   2
#define HC   128
#define GG   128
#define L1S  256
#define L2S  128
#define OUTS 10
#define NEG_SLOPE 0.2f
#define NB   49             // scan blocks: 49*1024 >= NN

// ---------------- static device scratch ----------------
__device__ int   g_is64;
__device__ int   g_deg[NN];
__device__ int   g_fill[NN];
__device__ int   g_ptr[NN + 1];
__device__ int   g_col[EP];
__device__ int   g_bsum[NB];
__device__ int   g_boff[NB];
__device__ int   g_gstart[GG + 1];
__device__ float g_in  [NN * HC];
__device__ __nv_bfloat16 g_hb[NN * HC];   // h in bf16 (gather payload)
__device__ float g_as  [NN * HH];
__device__ float g_ad  [NN * HH];
__device__ float g_e   [EP * HH];         // deg>32 fallback only

__device__ __forceinline__ float lrelu(float v) {
    return v > 0.f ? v : NEG_SLOPE * v;
}

__device__ __forceinline__ int load_idx(const void* p, long long i, int is64) {
    return is64 ? (int)((const long long*)p)[i] : ((const int*)p)[i];
}

__device__ __forceinline__ unsigned f2tf32(float x) {
    unsigned r;
    asm("cvt.rna.tf32.f32 %0, %1;" : "=r"(r) : "f"(x));
    return r;
}

__device__ __forceinline__ void mma_tf32(float* d,
                                         const unsigned* a,
                                         const unsigned* b) {
    asm volatile(
        "mma.sync.aligned.m16n8k8.row.col.f32.tf32.tf32.f32 "
        "{%0,%1,%2,%3}, {%4,%5,%6,%7}, {%8,%9}, {%0,%1,%2,%3};\n"
        : "+f"(d[0]), "+f"(d[1]), "+f"(d[2]), "+f"(d[3])
        : "r"(a[0]), "r"(a[1]), "r"(a[2]), "r"(a[3]),
          "r"(b[0]), "r"(b[1]));
}

// accumulate a * (4 bf16 packed at p)
__device__ __forceinline__ void acc_bf16(float4& acc, float a, const __nv_bfloat16* p) {
    uint2 raw = *(const uint2*)p;
    __nv_bfloat162 p0 = *reinterpret_cast<__nv_bfloat162*>(&raw.x);
    __nv_bfloat162 p1 = *reinterpret_cast<__nv_bfloat162*>(&raw.y);
    float2 f0 = __bfloat1622float2(p0);
    float2 f1 = __bfloat1622float2(p1);
    acc.x += a * f0.x; acc.y += a * f0.y;
    acc.z += a * f1.x; acc.w += a * f1.y;
}

// ---------------- dtype sniffing (parallel) ----------------
__global__ void k_detect(const void* edge) {
    __shared__ int any_hi;
    int tid = threadIdx.x;
    if (tid == 0) any_hi = 0;
    __syncthreads();
    const unsigned long long* q = (const unsigned long long*)edge;
    int bad = 0;
    for (int i = tid; i < 1024; i += 256)
        if (q[i] >> 32) bad = 1;
    if (bad) any_hi = 1;
    __syncthreads();
    if (tid == 0) g_is64 = any_hi ? 0 : 1;
}

// ---------------- node prep: zero degrees + graph boundaries -------------
__global__ void k_prep(const void* batch) {
    int i = blockIdx.x * blockDim.x + threadIdx.x;
    if (i < NN) g_deg[i] = 0;
    if (i > NN) return;
    int is64 = g_is64;
    if (i == 0) {
        int b0 = load_idx(batch, 0, is64);
        for (int g = 0; g <= b0; g++) g_gstart[g] = 0;
    } else {
        int bp = load_idx(batch, i - 1, is64);
        if (i == NN) {
            for (int g = bp + 1; g <= GG; g++) g_gstart[g] = NN;
        } else {
            int b = load_idx(batch, i, is64);
            if (b != bp)
                for (int g = bp + 1; g <= b; g++) g_gstart[g] = i;
        }
    }
}

// ---------------- degree histogram ----------------
__global__ void k_deg(const void* edge) {
    int i = blockIdx.x * blockDim.x + threadIdx.x;
    if (i >= EP) return;
    int d;
    if (i < EE) d = load_idx(edge, (long long)EE + i, g_is64);
    else        d = i - EE;
    atomicAdd(&g_deg[d], 1);
}

// ---------------- multi-block exclusive scan (3 phases) ----------
__global__ void __launch_bounds__(1024) k_scanA() {
    __shared__ int wsum[32];
    int i = blockIdx.x * 1024 + threadIdx.x;
    int lane = threadIdx.x & 31, wid = threadIdx.x >> 5;
    int v = (i < NN) ? g_deg[i] : 0;
    int inc = v;
#pragma unroll
    for (int o = 1; o < 32; o <<= 1) {
        int t = __shfl_up_sync(0xFFFFFFFFu, inc, o);
        if (lane >= o) inc += t;
    }
    if (lane == 31) wsum[wid] = inc;
    __syncthreads();
    if (wid == 0) {
        int wv = wsum[lane];
        int winc = wv;
#pragma unroll
        for (int o = 1; o < 32; o <<= 1) {
            int t = __shfl_up_sync(0xFFFFFFFFu, winc, o);
            if (lane >= o) winc += t;
        }
        wsum[lane] = winc - wv;
        if (lane == 31) g_bsum[blockIdx.x] = winc;
    }
    __syncthreads();
    int ex = inc - v + wsum[wid];
    if (i < NN) g_ptr[i] = ex;
}

__global__ void k_scanB() {
    __shared__ int s[64];
    int t = threadIdx.x;
    int v = (t < NB) ? g_bsum[t] : 0;
    s[t] = v;
    __syncthreads();
    for (int o = 1; o < 64; o <<= 1) {
        int x = (t >= o) ? s[t - o] : 0;
        __syncthreads();
        s[t] += x;
        __syncthreads();
    }
    if (t < NB) g_boff[t] = s[t] - v;
    if (t == 63) g_ptr[NN] = s[63];
}

__global__ void __launch_bounds__(1024) k_scanC() {
    int i = blockIdx.x * 1024 + threadIdx.x;
    if (i >= NN) return;
    g_ptr[i] += g_boff[i >> 10];
    g_fill[i] = 0;
}

// ---------------- scatter into CSR ----------------
__global__ void k_scatter(const void* edge) {
    int i = blockIdx.x * blockDim.x + threadIdx.x;
    if (i >= EP) return;
    int s, d;
    if (i < EE) {
        int is64 = g_is64;
        s = load_idx(edge, i, is64);
        d = load_idx(edge, (long long)EE + i, is64);
    } else {
        s = i - EE; d = s;
    }
    int pos = atomicAdd(&g_fill[d], 1);
    g_col[g_ptr[d] + pos] = s;
}

// ---------------- tf32 tensor-core GEMM, register-staged pipeline --------
// h[M,128] = A[M,128] @ W[128,128]; 128x128 tile, BK=16, 2-stage smem.
// Per chunk: store staged regs->smem (cvt), sync, issue next chunk's global
// loads into regs, compute current chunk (loads overlap compute).
#define BKC 16
#define AS_STRIDE 20      // banks: g*20+t all distinct for g0..7,t0..3
#define BS_STRIDE 136     // banks: 8t+g all distinct
__global__ void __launch_bounds__(256) k_gemm(const float* __restrict__ A,
                                              const float* __restrict__ W,
                                              const float* __restrict__ a_src,
                                              const float* __restrict__ a_dst,
                                              int use_x) {
    __shared__ unsigned As[2][128 * AS_STRIDE];
    __shared__ unsigned Bs[2][BKC * BS_STRIDE];
    __shared__ float s_as[128][2];
    __shared__ float s_ad[128][2];

    const float* Ap = use_x ? A : (const float*)g_in;
    int row0 = blockIdx.x * 128;
    int tid = threadIdx.x;
    int wid = tid >> 5, lane = tid & 31;
    int g = lane >> 2, t = lane & 3;
    int wr = wid >> 2, wc = wid & 3;
    int head = wc >> 1;

    if (tid < 128) { s_as[tid][0] = 0.f; s_as[tid][1] = 0.f;
                     s_ad[tid][0] = 0.f; s_ad[tid][1] = 0.f; }

    // loader indices
    int ar = tid >> 1;                 // A row 0..127
    int ac = (tid & 1) * 8;            // A k offset 0 or 8 (2 float4)
    int br0 = tid >> 5, bn0 = (tid & 31) << 2;          // B idx = tid
    int br1 = (tid + 256) >> 5, bn1 = ((tid + 256) & 31) << 2;
    int agrow = row0 + ar;
    bool aval = (agrow < NN);

    float4 ra0, ra1, rb0, rb1;
    auto load_chunk = [&](int k0) {
        if (aval) {
            ra0 = *(const float4*)&Ap[agrow * HC + k0 + ac];
            ra1 = *(const float4*)&Ap[agrow * HC + k0 + ac + 4];
        } else {
            ra0 = make_float4(0.f, 0.f, 0.f, 0.f);
            ra1 = ra0;
        }
        rb0 = *(const float4*)&W[(k0 + br0) * HC + bn0];
        rb1 = *(const float4*)&W[(k0 + br1) * HC + bn1];
    };
    auto store_chunk = [&](int st) {
        unsigned* pa = &As[st][ar * AS_STRIDE + ac];
        pa[0] = f2tf32(ra0.x); pa[1] = f2tf32(ra0.y);
        pa[2] = f2tf32(ra0.z); pa[3] = f2tf32(ra0.w);
        pa[4] = f2tf32(ra1.x); pa[5] = f2tf32(ra1.y);
        pa[6] = f2tf32(ra1.z); pa[7] = f2tf32(ra1.w);
        unsigned* pb0 = &Bs[st][br0 * BS_STRIDE + bn0];
        pb0[0] = f2tf32(rb0.x); pb0[1] = f2tf32(rb0.y);
        pb0[2] = f2tf32(rb0.z); pb0[3] = f2tf32(rb0.w);
        unsigned* pb1 = &Bs[st][br1 * BS_STRIDE + bn1];
        pb1[0] = f2tf32(rb1.x); pb1[1] = f2tf32(rb1.y);
        pb1[2] = f2tf32(rb1.z); pb1[3] = f2tf32(rb1.w);
    };

    float acc[4][4][4];
#pragma unroll
    for (int mf = 0; mf < 4; mf++)
#pragma unroll
        for (int nf = 0; nf < 4; nf++)
#pragma unroll
            for (int c = 0; c < 4; c++) acc[mf][nf][c] = 0.f;

    load_chunk(0);
    for (int c = 0; c < 8; c++) {
        int st = c & 1;
        store_chunk(st);
        __syncthreads();
        if (c < 7) load_chunk((c + 1) * BKC);   // in-flight during compute

        const unsigned* Af = As[st];
        const unsigned* Bf = Bs[st];
#pragma unroll
        for (int kk = 0; kk < BKC; kk += 8) {
            unsigned af[4][4];
#pragma unroll
            for (int mf = 0; mf < 4; mf++) {
                int r = wr * 64 + mf * 16 + g;
                af[mf][0] = Af[r * AS_STRIDE + kk + t];
                af[mf][1] = Af[(r + 8) * AS_STRIDE + kk + t];
                af[mf][2] = Af[r * AS_STRIDE + kk + t + 4];
                af[mf][3] = Af[(r + 8) * AS_STRIDE + kk + t + 4];
            }
            unsigned bf[4][2];
#pragma unroll
            for (int nf = 0; nf < 4; nf++) {
                int n = wc * 32 + nf * 8 + g;
                bf[nf][0] = Bf[(kk + t) * BS_STRIDE + n];
                bf[nf][1] = Bf[(kk + t + 4) * BS_STRIDE + n];
            }
#pragma unroll
            for (int mf = 0; mf < 4; mf++)
#pragma unroll
                for (int nf = 0; nf < 4; nf++)
                    mma_tf32(acc[mf][nf], af[mf], bf[nf]);
        }
    }
    __syncthreads();

    // epilogue: store h (bf16) + fused alpha
    float asv[8], adv[8];
#pragma unroll
    for (int nf = 0; nf < 4; nf++) {
#pragma unroll
        for (int c = 0; c < 2; c++) {
            int col = wc * 32 + nf * 8 + 2 * t + c;
            asv[nf * 2 + c] = a_src[col];
            adv[nf * 2 + c] = a_dst[col];
        }
    }

#pragma unroll
    for (int mf = 0; mf < 4; mf++) {
#pragma unroll
        for (int r = 0; r < 2; r++) {
            int rloc = wr * 64 + mf * 16 + g + 8 * r;
            int grow = row0 + rloc;
            float ps = 0.f, pd = 0.f;
#pragma unroll
            for (int nf = 0; nf < 4; nf++) {
                float v0 = acc[mf][nf][2 * r];
                float v1 = acc[mf][nf][2 * r + 1];
                ps += v0 * asv[nf * 2] + v1 * asv[nf * 2 + 1];
                pd += v0 * adv[nf * 2] + v1 * adv[nf * 2 + 1];
                if (grow < NN) {
                    int col = wc * 32 + nf * 8 + 2 * t;
                    *(__nv_bfloat162*)&g_hb[grow * HC + col] =
                        __floats2bfloat162_rn(v0, v1);
                }
            }
            ps += __shfl_xor_sync(0xFFFFFFFFu, ps, 1);
            ps += __shfl_xor_sync(0xFFFFFFFFu, ps, 2);
            pd += __shfl_xor_sync(0xFFFFFFFFu, pd, 1);
            pd += __shfl_xor_sync(0xFFFFFFFFu, pd, 2);
            if (t == 0) {
                atomicAdd(&s_as[rloc][head], ps);
                atomicAdd(&s_ad[rloc][head], pd);
            }
        }
    }
    __syncthreads();

    if (tid < 128) {
        int grow = row0 + tid;
        if (grow < NN) {
            *(float2*)&g_as[grow * 2] = make_float2(s_as[tid][0], s_as[tid][1]);
            *(float2*)&g_ad[grow * 2] = make_float2(s_ad[tid][0], s_ad[tid][1]);
        }
    }
}

// ---------------- fused softmax + aggregation: warp per dst node ---------
// (proven 274.4us form)
__global__ void __launch_bounds__(256) k_node(const float* __restrict__ b) {
    __shared__ int    sh_s[8][32];
    __shared__ float2 sh_a[8][32];
    int w = (blockIdx.x * blockDim.x + threadIdx.x) >> 5;
    if (w >= NN) return;
    int lane = threadIdx.x & 31;
    int wl = (threadIdx.x >> 5);
    int beg = g_ptr[w], end = g_ptr[w + 1];
    int deg = end - beg;
    float2 ad = *(const float2*)&g_ad[w * 2];

    int f = lane * 4;
    int head = f >> 6;
    float4 acc = make_float4(0.f, 0.f, 0.f, 0.f);

    if (deg <= 32) {
        int s = 0;
        float e0 = -INFINITY, e1 = -INFINITY;
        if (lane < deg) {
            s = g_col[beg + lane];
            float2 as = *(const float2*)&g_as[s * 2];
            e0 = lrelu(as.x + ad.x);
            e1 = lrelu(as.y + ad.y);
        }
        float m0 = e0, m1 = e1;
#pragma unroll
        for (int o = 16; o; o >>= 1) {
            m0 = fmaxf(m0, __shfl_xor_sync(0xFFFFFFFFu, m0, o));
            m1 = fmaxf(m1, __shfl_xor_sync(0xFFFFFFFFu, m1, o));
        }
        float x0 = (lane < deg) ? __expf(e0 - m0) : 0.f;
        float x1 = (lane < deg) ? __expf(e1 - m1) : 0.f;
        float s0 = x0, s1 = x1;
#pragma unroll
        for (int o = 16; o; o >>= 1) {
            s0 += __shfl_xor_sync(0xFFFFFFFFu, s0, o);
            s1 += __shfl_xor_sync(0xFFFFFFFFu, s1, o);
        }
        sh_s[wl][lane] = s;
        sh_a[wl][lane] = make_float2(x0 / (s0 + 1e-16f), x1 / (s1 + 1e-16f));
        __syncwarp();

        int j = 0;
        for (; j + 3 < deg; j += 4) {
            int    i0 = sh_s[wl][j],     i1 = sh_s[wl][j + 1];
            int    i2 = sh_s[wl][j + 2], i3 = sh_s[wl][j + 3];
            float2 w0 = sh_a[wl][j],     w1 = sh_a[wl][j + 1];
            float2 w2 = sh_a[wl][j + 2], w3 = sh_a[wl][j + 3];
            float a0 = head ? w0.y : w0.x;
            float a1 = head ? w1.y : w1.x;
            float a2 = head ? w2.y : w2.x;
            float a3 = head ? w3.y : w3.x;
            acc_bf16(acc, a0, &g_hb[i0 * HC + f]);
            acc_bf16(acc, a1, &g_hb[i1 * HC + f]);
            acc_bf16(acc, a2, &g_hb[i2 * HC + f]);
            acc_bf16(acc, a3, &g_hb[i3 * HC + f]);
        }
        for (; j < deg; j++) {
            int    sj = sh_s[wl][j];
            float2 wj = sh_a[wl][j];
            float  aj = head ? wj.y : wj.x;
            acc_bf16(acc, aj, &g_hb[sj * HC + f]);
        }
    } else {
        float m0 = -INFINITY, m1 = -INFINITY;
        for (int j = beg + lane; j < end; j += 32) {
            int s = g_col[j];
            float2 as = *(const float2*)&g_as[s * 2];
            float e0 = lrelu(as.x + ad.x);
            float e1 = lrelu(as.y + ad.y);
            *(float2*)&g_e[j * 2] = make_float2(e0, e1);
            m0 = fmaxf(m0, e0); m1 = fmaxf(m1, e1);
        }
#pragma unroll
        for (int o = 16; o; o >>= 1) {
            m0 = fmaxf(m0, __shfl_xor_sync(0xFFFFFFFFu, m0, o));
            m1 = fmaxf(m1, __shfl_xor_sync(0xFFFFFFFFu, m1, o));
        }
        float s0 = 0.f, s1 = 0.f;
        for (int j = beg + lane; j < end; j += 32) {
            float2 e = *(const float2*)&g_e[j * 2];
            float x0 = __expf(e.x - m0);
            float x1 = __expf(e.y - m1);
            *(float2*)&g_e[j * 2] = make_float2(x0, x1);
            s0 += x0; s1 += x1;
        }
#pragma unroll
        for (int o = 16; o; o >>= 1) {
            s0 += __shfl_xor_sync(0xFFFFFFFFu, s0, o);
            s1 += __shfl_xor_sync(0xFFFFFFFFu, s1, o);
        }
        float inv = head ? 1.f / (s1 + 1e-16f) : 1.f / (s0 + 1e-16f);
        __syncwarp();
        for (int j = beg; j < end; j++) {
            int s = g_col[j];
            float a = g_e[j * 2 + head] * inv;
            acc_bf16(acc, a, &g_hb[s * HC + f]);
        }
    }

    float4 bb = *(const float4*)&b[f];
    acc.x = fmaxf(acc.x + bb.x, 0.f);
    acc.y = fmaxf(acc.y + bb.y, 0.f);
    acc.z = fmaxf(acc.z + bb.z, 0.f);
    acc.w = fmaxf(acc.w + bb.w, 0.f);
    *(float4*)&g_in[w * HC + f] = acc;
}

// ---------------- fused pool + MLP head ----------------
__global__ void __launch_bounds__(256) k_head(
        const float* __restrict__ w1, const float* __restrict__ b1,
        const float* __restrict__ w2, const float* __restrict__ b2,
        const float* __restrict__ w3, const float* __restrict__ b3,
        float* __restrict__ out) {
    __shared__ float pool[HC];
    __shared__ float r1[L1S];
    __shared__ float r2[L2S];
    int g = blockIdx.x, tid = threadIdx.x;
    int beg = g_gstart[g], end = g_gstart[g + 1];

    if (tid < HC) {
        float sum = 0.f;
#pragma unroll 4
        for (int n = beg; n < end; n++) sum += g_in[n * HC + tid];
        pool[tid] = sum / fmaxf((float)(end - beg), 1.f);
    }
    __syncthreads();

    {
        float acc = 0.f;
#pragma unroll 4
        for (int k = 0; k < HC; k++) acc += pool[k] * w1[k * L1S + tid];
        acc += b1[tid];
        r1[tid] = acc > 0.f ? acc : 0.f;
    }
    __syncthreads();

    if (tid < L2S) {
        float acc = 0.f;
#pragma unroll 4
        for (int k = 0; k < L1S; k++) acc += r1[k] * w2[k * L2S + tid];
        acc += b2[tid];
        r2[tid] = acc > 0.f ? acc : 0.f;
    }
    __syncthreads();

    if (tid < OUTS) {
        float acc = 0.f;
#pragma unroll 4
        for (int k = 0; k < L2S; k++) acc += r2[k] * w3[k * OUTS + tid];
        out[g * OUTS + tid] = acc + b3[tid];
    }
}

// ---------------- host orchestration (R7 ordering) ----------------
extern "C" void kernel_launch(void* const* d_in, const int* in_sizes, int n_in,
                              void* d_out, int out_size) {
    const float* x       = (const float*)d_in[0];
    const void*  edge    = d_in[1];
    const void*  batch   = d_in[2];
    const float* W[3]    = {(const float*)d_in[3], (const float*)d_in[7],  (const float*)d_in[11]};
    const float* asrc[3] = {(const float*)d_in[4], (const float*)d_in[8],  (const float*)d_in[12]};
    const float* adst[3] = {(const float*)d_in[5], (const float*)d_in[9],  (const float*)d_in[13]};
    const float* bias[3] = {(const float*)d_in[6], (const float*)d_in[10], (const float*)d_in[14]};
    const float* lin1_w = (const float*)d_in[15];
    const float* lin1_b = (const float*)d_in[16];
    const float* lin2_w = (const float*)d_in[17];
    const float* lin2_b = (const float*)d_in[18];
    const float* out_w  = (const float*)d_in[19];
    const float* out_b  = (const float*)d_in[20];
    float* out = (float*)d_out;

    const int edge_blocks  = (EP + 255) / 256;
    const int gemm_blocks  = (NN + 127) / 128;
    const int warp8_blocks = (NN + 7) / 8;

    k_detect<<<1, 256>>>(edge);
    k_prep<<<(NN + 256) / 256, 256>>>(batch);
    k_deg<<<edge_blocks, 256>>>(edge);
    k_scanA<<<NB, 1024>>>();
    k_scanB<<<1, 64>>>();
    k_scanC<<<NB, 1024>>>();
    k_scatter<<<edge_blocks, 256>>>(edge);

    for (int l = 0; l < 3; l++) {
        k_gemm<<<gemm_blocks, 256>>>(x, W[l], asrc[l], adst[l], l == 0 ? 1 : 0);
        k_node<<<warp8_blocks, 256>>>(bias[l]);
    }

    k_head<<<GG, 256>>>(lin1_w, lin1_b, lin2_w, lin2_b, out_w, out_b, out);
}

// round 14
// speedup vs baseline: 1.0450x; 1.0450x over previous
#include <cuda_runtime.h>
#include <cuda_bf16.h>
#include <math.h>

// ---------------- problem constants ----------------
#define NN   50000
#define EE   800000
#define EP   (EE + NN)      // 850000
#define HH   2
#define HC   128
#define GG   128
#define L1S  256
#define L2S  128
#define OUTS 10
#define NEG_SLOPE 0.2f
#define NB   49             // scan blocks: 49*1024 >= NN

// ---------------- static device scratch ----------------
__device__ int   g_is64;
__device__ int   g_deg[NN];
__device__ int   g_fill[NN];
__device__ int   g_ptr[NN + 1];
__device__ int   g_col[EP];
__device__ int   g_bsum[NB];
__device__ int   g_boff[NB];
__device__ int   g_gstart[GG + 1];
__device__ float g_in  [NN * HC];
__device__ __nv_bfloat16 g_hb[NN * HC];   // h in bf16 (gather payload)
__device__ float g_as  [NN * HH];
__device__ float g_ad  [NN * HH];
__device__ float g_e   [EP * HH];         // deg>32 fallback only

__device__ __forceinline__ float lrelu(float v) {
    return v > 0.f ? v : NEG_SLOPE * v;
}

__device__ __forceinline__ int load_idx(const void* p, long long i, int is64) {
    return is64 ? (int)((const long long*)p)[i] : ((const int*)p)[i];
}

__device__ __forceinline__ unsigned f2tf32(float x) {
    unsigned r;
    asm("cvt.rna.tf32.f32 %0, %1;" : "=r"(r) : "f"(x));
    return r;
}

__device__ __forceinline__ void mma_tf32(float* d,
                                         const unsigned* a,
                                         const unsigned* b) {
    asm volatile(
        "mma.sync.aligned.m16n8k8.row.col.f32.tf32.tf32.f32 "
        "{%0,%1,%2,%3}, {%4,%5,%6,%7}, {%8,%9}, {%0,%1,%2,%3};\n"
        : "+f"(d[0]), "+f"(d[1]), "+f"(d[2]), "+f"(d[3])
        : "r"(a[0]), "r"(a[1]), "r"(a[2]), "r"(a[3]),
          "r"(b[0]), "r"(b[1]));
}

// accumulate a * (4 bf16 packed at p)
__device__ __forceinline__ void acc_bf16(float4& acc, float a, const __nv_bfloat16* p) {
    uint2 raw = *(const uint2*)p;
    __nv_bfloat162 p0 = *reinterpret_cast<__nv_bfloat162*>(&raw.x);
    __nv_bfloat162 p1 = *reinterpret_cast<__nv_bfloat162*>(&raw.y);
    float2 f0 = __bfloat1622float2(p0);
    float2 f1 = __bfloat1622float2(p1);
    acc.x += a * f0.x; acc.y += a * f0.y;
    acc.z += a * f1.x; acc.w += a * f1.y;
}

// ---------------- dtype sniffing (parallel) ----------------
__global__ void k_detect(const void* edge) {
    __shared__ int any_hi;
    int tid = threadIdx.x;
    if (tid == 0) any_hi = 0;
    __syncthreads();
    const unsigned long long* q = (const unsigned long long*)edge;
    int bad = 0;
    for (int i = tid; i < 1024; i += 256)
        if (q[i] >> 32) bad = 1;
    if (bad) any_hi = 1;
    __syncthreads();
    if (tid == 0) g_is64 = any_hi ? 0 : 1;
}

// ---------------- node prep: zero degrees + graph boundaries -------------
__global__ void k_prep(const void* batch) {
    int i = blockIdx.x * blockDim.x + threadIdx.x;
    if (i < NN) g_deg[i] = 0;
    if (i > NN) return;
    int is64 = g_is64;
    if (i == 0) {
        int b0 = load_idx(batch, 0, is64);
        for (int g = 0; g <= b0; g++) g_gstart[g] = 0;
    } else {
        int bp = load_idx(batch, i - 1, is64);
        if (i == NN) {
            for (int g = bp + 1; g <= GG; g++) g_gstart[g] = NN;
        } else {
            int b = load_idx(batch, i, is64);
            if (b != bp)
                for (int g = bp + 1; g <= b; g++) g_gstart[g] = i;
        }
    }
}

// ---------------- degree histogram ----------------
__global__ void k_deg(const void* edge) {
    int i = blockIdx.x * blockDim.x + threadIdx.x;
    if (i >= EP) return;
    int d;
    if (i < EE) d = load_idx(edge, (long long)EE + i, g_is64);
    else        d = i - EE;
    atomicAdd(&g_deg[d], 1);
}

// ---------------- multi-block exclusive scan ----------------
__global__ void __launch_bounds__(1024) k_scanA() {
    __shared__ int wsum[32];
    int i = blockIdx.x * 1024 + threadIdx.x;
    int lane = threadIdx.x & 31, wid = threadIdx.x >> 5;
    int v = (i < NN) ? g_deg[i] : 0;
    int inc = v;
#pragma unroll
    for (int o = 1; o < 32; o <<= 1) {
        int t = __shfl_up_sync(0xFFFFFFFFu, inc, o);
        if (lane >= o) inc += t;
    }
    if (lane == 31) wsum[wid] = inc;
    __syncthreads();
    if (wid == 0) {
        int wv = wsum[lane];
        int winc = wv;
#pragma unroll
        for (int o = 1; o < 32; o <<= 1) {
            int t = __shfl_up_sync(0xFFFFFFFFu, winc, o);
            if (lane >= o) winc += t;
        }
        wsum[lane] = winc - wv;
        if (lane == 31) g_bsum[blockIdx.x] = winc;
    }
    __syncthreads();
    int ex = inc - v + wsum[wid];
    if (i < NN) g_ptr[i] = ex;
}

__global__ void k_scanB() {
    __shared__ int s[64];
    int t = threadIdx.x;
    int v = (t < NB) ? g_bsum[t] : 0;
    s[t] = v;
    __syncthreads();
    for (int o = 1; o < 64; o <<= 1) {
        int x = (t >= o) ? s[t - o] : 0;
        __syncthreads();
        s[t] += x;
        __syncthreads();
    }
    if (t < NB) g_boff[t] = s[t] - v;
    if (t == 63) g_ptr[NN] = s[63];
}

__global__ void __launch_bounds__(1024) k_scanC() {
    int i = blockIdx.x * 1024 + threadIdx.x;
    if (i >= NN) return;
    g_ptr[i] += g_boff[i >> 10];
    g_fill[i] = 0;
}

// ---------------- scatter into CSR ----------------
__global__ void k_scatter(const void* edge) {
    int i = blockIdx.x * blockDim.x + threadIdx.x;
    if (i >= EP) return;
    int s, d;
    if (i < EE) {
        int is64 = g_is64;
        s = load_idx(edge, i, is64);
        d = load_idx(edge, (long long)EE + i, is64);
    } else {
        s = i - EE; d = s;
    }
    int pos = atomicAdd(&g_fill[d], 1);
    g_col[g_ptr[d] + pos] = s;
}

// ---------------- tf32 tensor-core GEMM + fused alpha (274us build) ------
#define AS_STRIDE 36
#define BS_STRIDE 136
__global__ void __launch_bounds__(256) k_gemm(const float* __restrict__ A,
                                              const float* __restrict__ W,
                                              const float* __restrict__ a_src,
                                              const float* __restrict__ a_dst,
                                              int use_x) {
    __shared__ unsigned As[128 * AS_STRIDE];
    __shared__ unsigned Bs[32 * BS_STRIDE];
    __shared__ float s_as[128][2];
    __shared__ float s_ad[128][2];

    const float* Ap = use_x ? A : (const float*)g_in;
    int row0 = blockIdx.x * 128;
    int tid = threadIdx.x;
    int wid = tid >> 5, lane = tid & 31;
    int g = lane >> 2, t = lane & 3;
    int wr = wid >> 2, wc = wid & 3;
    int head = wc >> 1;

    if (tid < 128) { s_as[tid][0] = 0.f; s_as[tid][1] = 0.f;
                     s_ad[tid][0] = 0.f; s_ad[tid][1] = 0.f; }

    float acc[4][4][4];
#pragma unroll
    for (int mf = 0; mf < 4; mf++)
#pragma unroll
        for (int nf = 0; nf < 4; nf++)
#pragma unroll
            for (int c = 0; c < 4; c++) acc[mf][nf][c] = 0.f;

    for (int k0 = 0; k0 < 128; k0 += 32) {
#pragma unroll
        for (int l = 0; l < 4; l++) {
            int idx = tid + l * 256;
            int row = idx >> 3;
            int k4 = (idx & 7) << 2;
            int grow = row0 + row;
            float4 v = (grow < NN) ? *(const float4*)&Ap[grow * HC + k0 + k4]
                                   : make_float4(0.f, 0.f, 0.f, 0.f);
            unsigned* p = &As[row * AS_STRIDE + k4];
            p[0] = f2tf32(v.x); p[1] = f2tf32(v.y);
            p[2] = f2tf32(v.z); p[3] = f2tf32(v.w);
        }
#pragma unroll
        for (int l = 0; l < 4; l++) {
            int idx = tid + l * 256;
            int k = idx >> 5;
            int n4 = (idx & 31) << 2;
            float4 v = *(const float4*)&W[(k0 + k) * HC + n4];
            unsigned* p = &Bs[k * BS_STRIDE + n4];
            p[0] = f2tf32(v.x); p[1] = f2tf32(v.y);
            p[2] = f2tf32(v.z); p[3] = f2tf32(v.w);
        }
        __syncthreads();

#pragma unroll
        for (int kk = 0; kk < 32; kk += 8) {
            unsigned af[4][4];
#pragma unroll
            for (int mf = 0; mf < 4; mf++) {
                int r = wr * 64 + mf * 16 + g;
                af[mf][0] = As[r * AS_STRIDE + kk + t];
                af[mf][1] = As[(r + 8) * AS_STRIDE + kk + t];
                af[mf][2] = As[r * AS_STRIDE + kk + t + 4];
                af[mf][3] = As[(r + 8) * AS_STRIDE + kk + t + 4];
            }
            unsigned bf[4][2];
#pragma unroll
            for (int nf = 0; nf < 4; nf++) {
                int n = wc * 32 + nf * 8 + g;
                bf[nf][0] = Bs[(kk + t) * BS_STRIDE + n];
                bf[nf][1] = Bs[(kk + t + 4) * BS_STRIDE + n];
            }
#pragma unroll
            for (int mf = 0; mf < 4; mf++)
#pragma unroll
                for (int nf = 0; nf < 4; nf++)
                    mma_tf32(acc[mf][nf], af[mf], bf[nf]);
        }
        __syncthreads();
    }

    float asv[8], adv[8];
#pragma unroll
    for (int nf = 0; nf < 4; nf++) {
#pragma unroll
        for (int c = 0; c < 2; c++) {
            int col = wc * 32 + nf * 8 + 2 * t + c;
            asv[nf * 2 + c] = a_src[col];
            adv[nf * 2 + c] = a_dst[col];
        }
    }

#pragma unroll
    for (int mf = 0; mf < 4; mf++) {
#pragma unroll
        for (int r = 0; r < 2; r++) {
            int rloc = wr * 64 + mf * 16 + g + 8 * r;
            int grow = row0 + rloc;
            float ps = 0.f, pd = 0.f;
#pragma unroll
            for (int nf = 0; nf < 4; nf++) {
                float v0 = acc[mf][nf][2 * r];
                float v1 = acc[mf][nf][2 * r + 1];
                ps += v0 * asv[nf * 2] + v1 * asv[nf * 2 + 1];
                pd += v0 * adv[nf * 2] + v1 * adv[nf * 2 + 1];
                if (grow < NN) {
                    int col = wc * 32 + nf * 8 + 2 * t;
                    *(__nv_bfloat162*)&g_hb[grow * HC + col] =
                        __floats2bfloat162_rn(v0, v1);
                }
            }
            ps += __shfl_xor_sync(0xFFFFFFFFu, ps, 1);
            ps += __shfl_xor_sync(0xFFFFFFFFu, ps, 2);
            pd += __shfl_xor_sync(0xFFFFFFFFu, pd, 1);
            pd += __shfl_xor_sync(0xFFFFFFFFu, pd, 2);
            if (t == 0) {
                atomicAdd(&s_as[rloc][head], ps);
                atomicAdd(&s_ad[rloc][head], pd);
            }
        }
    }
    __syncthreads();

    if (tid < 128) {
        int grow = row0 + tid;
        if (grow < NN) {
            *(float2*)&g_as[grow * 2] = make_float2(s_as[tid][0], s_as[tid][1]);
            *(float2*)&g_ad[grow * 2] = make_float2(s_ad[tid][0], s_ad[tid][1]);
        }
    }
}

// ---------------- fused softmax + aggregation: warp per dst node ---------
__global__ void __launch_bounds__(256) k_node(const float* __restrict__ b) {
    __shared__ int    sh_s[8][32];
    __shared__ float2 sh_a[8][32];
    int w = (blockIdx.x * blockDim.x + threadIdx.x) >> 5;
    if (w >= NN) return;
    int lane = threadIdx.x & 31;
    int wl = (threadIdx.x >> 5);
    int beg = g_ptr[w], end = g_ptr[w + 1];
    int deg = end - beg;
    float2 ad = *(const float2*)&g_ad[w * 2];

    int f = lane * 4;
    int head = f >> 6;
    float4 acc = make_float4(0.f, 0.f, 0.f, 0.f);

    if (deg <= 32) {
        int s = 0;
        float e0 = -INFINITY, e1 = -INFINITY;
        if (lane < deg) {
            s = g_col[beg + lane];
            float2 as = *(const float2*)&g_as[s * 2];
            e0 = lrelu(as.x + ad.x);
            e1 = lrelu(as.y + ad.y);
        }
        float m0 = e0, m1 = e1;
#pragma unroll
        for (int o = 16; o; o >>= 1) {
            m0 = fmaxf(m0, __shfl_xor_sync(0xFFFFFFFFu, m0, o));
            m1 = fmaxf(m1, __shfl_xor_sync(0xFFFFFFFFu, m1, o));
        }
        float x0 = (lane < deg) ? __expf(e0 - m0) : 0.f;
        float x1 = (lane < deg) ? __expf(e1 - m1) : 0.f;
        float s0 = x0, s1 = x1;
#pragma unroll
        for (int o = 16; o; o >>= 1) {
            s0 += __shfl_xor_sync(0xFFFFFFFFu, s0, o);
            s1 += __shfl_xor_sync(0xFFFFFFFFu, s1, o);
        }
        sh_s[wl][lane] = s;
        sh_a[wl][lane] = make_float2(x0 / (s0 + 1e-16f), x1 / (s1 + 1e-16f));
        __syncwarp();

        int j = 0;
        for (; j + 3 < deg; j += 4) {
            int    i0 = sh_s[wl][j],     i1 = sh_s[wl][j + 1];
            int    i2 = sh_s[wl][j + 2], i3 = sh_s[wl][j + 3];
            float2 w0 = sh_a[wl][j],     w1 = sh_a[wl][j + 1];
            float2 w2 = sh_a[wl][j + 2], w3 = sh_a[wl][j + 3];
            float a0 = head ? w0.y : w0.x;
            float a1 = head ? w1.y : w1.x;
            float a2 = head ? w2.y : w2.x;
            float a3 = head ? w3.y : w3.x;
            acc_bf16(acc, a0, &g_hb[i0 * HC + f]);
            acc_bf16(acc, a1, &g_hb[i1 * HC + f]);
            acc_bf16(acc, a2, &g_hb[i2 * HC + f]);
            acc_bf16(acc, a3, &g_hb[i3 * HC + f]);
        }
        for (; j < deg; j++) {
            int    sj = sh_s[wl][j];
            float2 wj = sh_a[wl][j];
            float  aj = head ? wj.y : wj.x;
            acc_bf16(acc, aj, &g_hb[sj * HC + f]);
        }
    } else {
        float m0 = -INFINITY, m1 = -INFINITY;
        for (int j = beg + lane; j < end; j += 32) {
            int s = g_col[j];
            float2 as = *(const float2*)&g_as[s * 2];
            float e0 = lrelu(as.x + ad.x);
            float e1 = lrelu(as.y + ad.y);
            *(float2*)&g_e[j * 2] = make_float2(e0, e1);
            m0 = fmaxf(m0, e0); m1 = fmaxf(m1, e1);
        }
#pragma unroll
        for (int o = 16; o; o >>= 1) {
            m0 = fmaxf(m0, __shfl_xor_sync(0xFFFFFFFFu, m0, o));
            m1 = fmaxf(m1, __shfl_xor_sync(0xFFFFFFFFu, m1, o));
        }
        float s0 = 0.f, s1 = 0.f;
        for (int j = beg + lane; j < end; j += 32) {
            float2 e = *(const float2*)&g_e[j * 2];
            float x0 = __expf(e.x - m0);
            float x1 = __expf(e.y - m1);
            *(float2*)&g_e[j * 2] = make_float2(x0, x1);
            s0 += x0; s1 += x1;
        }
#pragma unroll
        for (int o = 16; o; o >>= 1) {
            s0 += __shfl_xor_sync(0xFFFFFFFFu, s0, o);
            s1 += __shfl_xor_sync(0xFFFFFFFFu, s1, o);
        }
        float inv = head ? 1.f / (s1 + 1e-16f) : 1.f / (s0 + 1e-16f);
        __syncwarp();
        for (int j = beg; j < end; j++) {
            int s = g_col[j];
            float a = g_e[j * 2 + head] * inv;
            acc_bf16(acc, a, &g_hb[s * HC + f]);
        }
    }

    float4 bb = *(const float4*)&b[f];
    acc.x = fmaxf(acc.x + bb.x, 0.f);
    acc.y = fmaxf(acc.y + bb.y, 0.f);
    acc.z = fmaxf(acc.z + bb.z, 0.f);
    acc.w = fmaxf(acc.w + bb.w, 0.f);
    *(float4*)&g_in[w * HC + f] = acc;
}

// ---------------- fused pool + MLP head ----------------
__global__ void __launch_bounds__(256) k_head(
        const float* __restrict__ w1, const float* __restrict__ b1,
        const float* __restrict__ w2, const float* __restrict__ b2,
        const float* __restrict__ w3, const float* __restrict__ b3,
        float* __restrict__ out) {
    __shared__ float pool[HC];
    __shared__ float r1[L1S];
    __shared__ float r2[L2S];
    int g = blockIdx.x, tid = threadIdx.x;
    int beg = g_gstart[g], end = g_gstart[g + 1];

    if (tid < HC) {
        float sum = 0.f;
        for (int n = beg; n < end; n++) sum += g_in[n * HC + tid];
        pool[tid] = sum / fmaxf((float)(end - beg), 1.f);
    }
    __syncthreads();

    {
        float acc = 0.f;
#pragma unroll 4
        for (int k = 0; k < HC; k++) acc += pool[k] * w1[k * L1S + tid];
        acc += b1[tid];
        r1[tid] = acc > 0.f ? acc : 0.f;
    }
    __syncthreads();

    if (tid < L2S) {
        float acc = 0.f;
#pragma unroll 4
        for (int k = 0; k < L1S; k++) acc += r1[k] * w2[k * L2S + tid];
        acc += b2[tid];
        r2[tid] = acc > 0.f ? acc : 0.f;
    }
    __syncthreads();

    if (tid < OUTS) {
        float acc = 0.f;
#pragma unroll 4
        for (int k = 0; k < L2S; k++) acc += r2[k] * w3[k * OUTS + tid];
        out[g * OUTS + tid] = acc + b3[tid];
    }
}

// ---------------- host orchestration ----------------
extern "C" void kernel_launch(void* const* d_in, const int* in_sizes, int n_in,
                              void* d_out, int out_size) {
    const float* x       = (const float*)d_in[0];
    const void*  edge    = d_in[1];
    const void*  batch   = d_in[2];
    const float* W[3]    = {(const float*)d_in[3], (const float*)d_in[7],  (const float*)d_in[11]};
    const float* asrc[3] = {(const float*)d_in[4], (const float*)d_in[8],  (const float*)d_in[12]};
    const float* adst[3] = {(const float*)d_in[5], (const float*)d_in[9],  (const float*)d_in[13]};
    const float* bias[3] = {(const float*)d_in[6], (const float*)d_in[10], (const float*)d_in[14]};
    const float* lin1_w = (const float*)d_in[15];
    const float* lin1_b = (const float*)d_in[16];
    const float* lin2_w = (const float*)d_in[17];
    const float* lin2_b = (const float*)d_in[18];
    const float* out_w  = (const float*)d_in[19];
    const float* out_b  = (const float*)d_in[20];
    float* out = (float*)d_out;

    const int edge_blocks  = (EP + 255) / 256;
    const int gemm_blocks  = (NN + 127) / 128;
    const int warp8_blocks = (NN + 7) / 8;

    k_detect<<<1, 256>>>(edge);
    k_prep<<<(NN + 256) / 256, 256>>>(batch);
    k_deg<<<edge_blocks, 256>>>(edge);
    k_scanA<<<NB, 1024>>>();
    k_scanB<<<1, 64>>>();
    k_scanC<<<NB, 1024>>>();
    k_scatter<<<edge_blocks, 256>>>(edge);

    for (int l = 0; l < 3; l++) {
        k_gemm<<<gemm_blocks, 256>>>(x, W[l], asrc[l], adst[l], l == 0 ? 1 : 0);
        k_node<<<warp8_blocks, 256>>>(bias[l]);
    }

    k_head<<<GG, 256>>>(lin1_w, lin1_b, lin2_w, lin2_b, out_w, out_b, out);
}

// round 15
// speedup vs baseline: 1.1022x; 1.0547x over previous
#include <cuda_runtime.h>
#include <cuda_bf16.h>
#include <math.h>

// ---------------- problem constants ----------------
#define NN   50000
#define EE   800000
#define EP   (EE + NN)      // 850000
#define HH   2
#define HC   128
#define GG   128
#define L1S  256
#define L2S  128
#define OUTS 10
#define NEG_SLOPE 0.2f
#define NB   49             // scan blocks: 49*1024 >= NN

// ---------------- static device scratch ----------------
__device__ int   g_is64;
__device__ int   g_deg[NN];
__device__ int   g_fill[NN];
__device__ int   g_ptr[NN + 1];
__device__ int   g_col[EP];
__device__ int   g_bsum[NB];
__device__ int   g_gstart[GG + 1];
__device__ __nv_bfloat16 g_inb[NN * HC];  // layer activations (bf16)
__device__ __nv_bfloat16 g_hb [NN * HC];  // h (bf16, gather payload)
__device__ float g_as  [NN * HH];
__device__ float g_ad  [NN * HH];
__device__ float g_e   [EP * HH];         // deg>32 fallback only

__device__ __forceinline__ float lrelu(float v) {
    return v > 0.f ? v : NEG_SLOPE * v;
}

__device__ __forceinline__ int load_idx(const void* p, long long i, int is64) {
    return is64 ? (int)((const long long*)p)[i] : ((const int*)p)[i];
}

__device__ __forceinline__ unsigned f2tf32(float x) {
    unsigned r;
    asm("cvt.rna.tf32.f32 %0, %1;" : "=r"(r) : "f"(x));
    return r;
}

__device__ __forceinline__ void mma_tf32(float* d,
                                         const unsigned* a,
                                         const unsigned* b) {
    asm volatile(
        "mma.sync.aligned.m16n8k8.row.col.f32.tf32.tf32.f32 "
        "{%0,%1,%2,%3}, {%4,%5,%6,%7}, {%8,%9}, {%0,%1,%2,%3};\n"
        : "+f"(d[0]), "+f"(d[1]), "+f"(d[2]), "+f"(d[3])
        : "r"(a[0]), "r"(a[1]), "r"(a[2]), "r"(a[3]),
          "r"(b[0]), "r"(b[1]));
}

// accumulate a * (4 bf16 packed at p)
__device__ __forceinline__ void acc_bf16(float4& acc, float a, const __nv_bfloat16* p) {
    uint2 raw = *(const uint2*)p;
    __nv_bfloat162 p0 = *reinterpret_cast<__nv_bfloat162*>(&raw.x);
    __nv_bfloat162 p1 = *reinterpret_cast<__nv_bfloat162*>(&raw.y);
    float2 f0 = __bfloat1622float2(p0);
    float2 f1 = __bfloat1622float2(p1);
    acc.x += a * f0.x; acc.y += a * f0.y;
    acc.z += a * f1.x; acc.w += a * f1.y;
}

// ---------------- dtype sniffing (parallel) ----------------
__global__ void k_detect(const void* edge) {
    __shared__ int any_hi;
    int tid = threadIdx.x;
    if (tid == 0) any_hi = 0;
    __syncthreads();
    const unsigned long long* q = (const unsigned long long*)edge;
    int bad = 0;
    for (int i = tid; i < 1024; i += 256)
        if (q[i] >> 32) bad = 1;
    if (bad) any_hi = 1;
    __syncthreads();
    if (tid == 0) g_is64 = any_hi ? 0 : 1;
}

// ---------------- node prep: zero degrees + graph boundaries -------------
__global__ void k_prep(const void* batch) {
    int i = blockIdx.x * blockDim.x + threadIdx.x;
    if (i < NN) g_deg[i] = 0;
    if (i > NN) return;
    int is64 = g_is64;
    if (i == 0) {
        int b0 = load_idx(batch, 0, is64);
        for (int g = 0; g <= b0; g++) g_gstart[g] = 0;
    } else {
        int bp = load_idx(batch, i - 1, is64);
        if (i == NN) {
            for (int g = bp + 1; g <= GG; g++) g_gstart[g] = NN;
        } else {
            int b = load_idx(batch, i, is64);
            if (b != bp)
                for (int g = bp + 1; g <= b; g++) g_gstart[g] = i;
        }
    }
}

// ---------------- degree histogram ----------------
__global__ void k_deg(const void* edge) {
    int i = blockIdx.x * blockDim.x + threadIdx.x;
    if (i >= EP) return;
    int d;
    if (i < EE) d = load_idx(edge, (long long)EE + i, g_is64);
    else        d = i - EE;
    atomicAdd(&g_deg[d], 1);
}

// ---------------- multi-block exclusive scan (2 phases) ----------
__global__ void __launch_bounds__(1024) k_scanA() {
    __shared__ int wsum[32];
    int i = blockIdx.x * 1024 + threadIdx.x;
    int lane = threadIdx.x & 31, wid = threadIdx.x >> 5;
    int v = (i < NN) ? g_deg[i] : 0;
    int inc = v;
#pragma unroll
    for (int o = 1; o < 32; o <<= 1) {
        int t = __shfl_up_sync(0xFFFFFFFFu, inc, o);
        if (lane >= o) inc += t;
    }
    if (lane == 31) wsum[wid] = inc;
    __syncthreads();
    if (wid == 0) {
        int wv = wsum[lane];
        int winc = wv;
#pragma unroll
        for (int o = 1; o < 32; o <<= 1) {
            int t = __shfl_up_sync(0xFFFFFFFFu, winc, o);
            if (lane >= o) winc += t;
        }
        wsum[lane] = winc - wv;
        if (lane == 31) g_bsum[blockIdx.x] = winc;
    }
    __syncthreads();
    int ex = inc - v + wsum[wid];
    if (i < NN) g_ptr[i] = ex;
}

// scanC folds the block-partial scan (thread 0 serial over 49 partials)
__global__ void __launch_bounds__(1024) k_scanC() {
    __shared__ int s[NB];
    __shared__ int boff;
    if (threadIdx.x < NB) s[threadIdx.x] = g_bsum[threadIdx.x];
    __syncthreads();
    if (threadIdx.x == 0) {
        int off = 0;
        for (int k = 0; k < blockIdx.x; k++) off += s[k];
        boff = off;
        if (blockIdx.x == NB - 1) {
            int tot = off;
            for (int k = blockIdx.x; k < NB; k++) tot += s[k];
            g_ptr[NN] = tot;
        }
    }
    __syncthreads();
    int i = blockIdx.x * 1024 + threadIdx.x;
    if (i >= NN) return;
    g_ptr[i] += boff;
    g_fill[i] = 0;
}

// ---------------- scatter into CSR ----------------
__global__ void k_scatter(const void* edge) {
    int i = blockIdx.x * blockDim.x + threadIdx.x;
    if (i >= EP) return;
    int s, d;
    if (i < EE) {
        int is64 = g_is64;
        s = load_idx(edge, i, is64);
        d = load_idx(edge, (long long)EE + i, is64);
    } else {
        s = i - EE; d = s;
    }
    int pos = atomicAdd(&g_fill[d], 1);
    g_col[g_ptr[d] + pos] = s;
}

// ---------------- tf32 tensor-core GEMM + fused alpha ---------------------
// A source: layer0 = x (fp32), layers 1-2 = g_inb (bf16, exact->tf32 shift).
#define AS_STRIDE 36
#define BS_STRIDE 136
__global__ void __launch_bounds__(256) k_gemm(const float* __restrict__ A,
                                              const float* __restrict__ W,
                                              const float* __restrict__ a_src,
                                              const float* __restrict__ a_dst,
                                              int use_x) {
    __shared__ unsigned As[128 * AS_STRIDE];
    __shared__ unsigned Bs[32 * BS_STRIDE];
    __shared__ float s_as[128][2];
    __shared__ float s_ad[128][2];

    int row0 = blockIdx.x * 128;
    int tid = threadIdx.x;
    int wid = tid >> 5, lane = tid & 31;
    int g = lane >> 2, t = lane & 3;
    int wr = wid >> 2, wc = wid & 3;
    int head = wc >> 1;

    if (tid < 128) { s_as[tid][0] = 0.f; s_as[tid][1] = 0.f;
                     s_ad[tid][0] = 0.f; s_ad[tid][1] = 0.f; }

    float acc[4][4][4];
#pragma unroll
    for (int mf = 0; mf < 4; mf++)
#pragma unroll
        for (int nf = 0; nf < 4; nf++)
#pragma unroll
            for (int c = 0; c < 4; c++) acc[mf][nf][c] = 0.f;

    for (int k0 = 0; k0 < 128; k0 += 32) {
        if (use_x) {
#pragma unroll
            for (int l = 0; l < 4; l++) {
                int idx = tid + l * 256;
                int row = idx >> 3;
                int k4 = (idx & 7) << 2;
                int grow = row0 + row;
                float4 v = (grow < NN) ? *(const float4*)&A[grow * HC + k0 + k4]
                                       : make_float4(0.f, 0.f, 0.f, 0.f);
                unsigned* p = &As[row * AS_STRIDE + k4];
                p[0] = f2tf32(v.x); p[1] = f2tf32(v.y);
                p[2] = f2tf32(v.z); p[3] = f2tf32(v.w);
            }
        } else {
#pragma unroll
            for (int l = 0; l < 4; l++) {
                int idx = tid + l * 256;
                int row = idx >> 3;
                int k4 = (idx & 7) << 2;
                int grow = row0 + row;
                uint2 r = (grow < NN)
                    ? *(const uint2*)&g_inb[grow * HC + k0 + k4]
                    : make_uint2(0u, 0u);
                unsigned* p = &As[row * AS_STRIDE + k4];
                p[0] = r.x << 16; p[1] = r.x & 0xFFFF0000u;   // bf16 -> tf32 exact
                p[2] = r.y << 16; p[3] = r.y & 0xFFFF0000u;
            }
        }
#pragma unroll
        for (int l = 0; l < 4; l++) {
            int idx = tid + l * 256;
            int k = idx >> 5;
            int n4 = (idx & 31) << 2;
            float4 v = *(const float4*)&W[(k0 + k) * HC + n4];
            unsigned* p = &Bs[k * BS_STRIDE + n4];
            p[0] = f2tf32(v.x); p[1] = f2tf32(v.y);
            p[2] = f2tf32(v.z); p[3] = f2tf32(v.w);
        }
        __syncthreads();

#pragma unroll
        for (int kk = 0; kk < 32; kk += 8) {
            unsigned af[4][4];
#pragma unroll
            for (int mf = 0; mf < 4; mf++) {
                int r = wr * 64 + mf * 16 + g;
                af[mf][0] = As[r * AS_STRIDE + kk + t];
                af[mf][1] = As[(r + 8) * AS_STRIDE + kk + t];
                af[mf][2] = As[r * AS_STRIDE + kk + t + 4];
                af[mf][3] = As[(r + 8) * AS_STRIDE + kk + t + 4];
            }
            unsigned bf[4][2];
#pragma unroll
            for (int nf = 0; nf < 4; nf++) {
                int n = wc * 32 + nf * 8 + g;
                bf[nf][0] = Bs[(kk + t) * BS_STRIDE + n];
                bf[nf][1] = Bs[(kk + t + 4) * BS_STRIDE + n];
            }
#pragma unroll
            for (int mf = 0; mf < 4; mf++)
#pragma unroll
                for (int nf = 0; nf < 4; nf++)
                    mma_tf32(acc[mf][nf], af[mf], bf[nf]);
        }
        __syncthreads();
    }

    float asv[8], adv[8];
#pragma unroll
    for (int nf = 0; nf < 4; nf++) {
#pragma unroll
        for (int c = 0; c < 2; c++) {
            int col = wc * 32 + nf * 8 + 2 * t + c;
            asv[nf * 2 + c] = a_src[col];
            adv[nf * 2 + c] = a_dst[col];
        }
    }

#pragma unroll
    for (int mf = 0; mf < 4; mf++) {
#pragma unroll
        for (int r = 0; r < 2; r++) {
            int rloc = wr * 64 + mf * 16 + g + 8 * r;
            int grow = row0 + rloc;
            float ps = 0.f, pd = 0.f;
#pragma unroll
            for (int nf = 0; nf < 4; nf++) {
                float v0 = acc[mf][nf][2 * r];
                float v1 = acc[mf][nf][2 * r + 1];
                ps += v0 * asv[nf * 2] + v1 * asv[nf * 2 + 1];
                pd += v0 * adv[nf * 2] + v1 * adv[nf * 2 + 1];
                if (grow < NN) {
                    int col = wc * 32 + nf * 8 + 2 * t;
                    *(__nv_bfloat162*)&g_hb[grow * HC + col] =
                        __floats2bfloat162_rn(v0, v1);
                }
            }
            ps += __shfl_xor_sync(0xFFFFFFFFu, ps, 1);
            ps += __shfl_xor_sync(0xFFFFFFFFu, ps, 2);
            pd += __shfl_xor_sync(0xFFFFFFFFu, pd, 1);
            pd += __shfl_xor_sync(0xFFFFFFFFu, pd, 2);
            if (t == 0) {
                atomicAdd(&s_as[rloc][head], ps);
                atomicAdd(&s_ad[rloc][head], pd);
            }
        }
    }
    __syncthreads();

    if (tid < 128) {
        int grow = row0 + tid;
        if (grow < NN) {
            *(float2*)&g_as[grow * 2] = make_float2(s_as[tid][0], s_as[tid][1]);
            *(float2*)&g_ad[grow * 2] = make_float2(s_ad[tid][0], s_ad[tid][1]);
        }
    }
}

// ---------------- fused softmax + aggregation: warp per dst node ---------
__global__ void __launch_bounds__(256) k_node(const float* __restrict__ b) {
    __shared__ int    sh_s[8][32];
    __shared__ float2 sh_a[8][32];
    int w = (blockIdx.x * blockDim.x + threadIdx.x) >> 5;
    if (w >= NN) return;
    int lane = threadIdx.x & 31;
    int wl = (threadIdx.x >> 5);
    int beg = g_ptr[w], end = g_ptr[w + 1];
    int deg = end - beg;
    float2 ad = *(const float2*)&g_ad[w * 2];

    int f = lane * 4;
    int head = f >> 6;
    float4 acc = make_float4(0.f, 0.f, 0.f, 0.f);

    if (deg <= 32) {
        int s = 0;
        float e0 = -INFINITY, e1 = -INFINITY;
        if (lane < deg) {
            s = g_col[beg + lane];
            float2 as = *(const float2*)&g_as[s * 2];
            e0 = lrelu(as.x + ad.x);
            e1 = lrelu(as.y + ad.y);
        }
        float m0 = e0, m1 = e1;
#pragma unroll
        for (int o = 16; o; o >>= 1) {
            m0 = fmaxf(m0, __shfl_xor_sync(0xFFFFFFFFu, m0, o));
            m1 = fmaxf(m1, __shfl_xor_sync(0xFFFFFFFFu, m1, o));
        }
        float x0 = (lane < deg) ? __expf(e0 - m0) : 0.f;
        float x1 = (lane < deg) ? __expf(e1 - m1) : 0.f;
        float s0 = x0, s1 = x1;
#pragma unroll
        for (int o = 16; o; o >>= 1) {
            s0 += __shfl_xor_sync(0xFFFFFFFFu, s0, o);
            s1 += __shfl_xor_sync(0xFFFFFFFFu, s1, o);
        }
        sh_s[wl][lane] = s;
        sh_a[wl][lane] = make_float2(x0 / (s0 + 1e-16f), x1 / (s1 + 1e-16f));
        __syncwarp();

        int j = 0;
        for (; j + 3 < deg; j += 4) {
            int    i0 = sh_s[wl][j],     i1 = sh_s[wl][j + 1];
            int    i2 = sh_s[wl][j + 2], i3 = sh_s[wl][j + 3];
            float2 w0 = sh_a[wl][j],     w1 = sh_a[wl][j + 1];
            float2 w2 = sh_a[wl][j + 2], w3 = sh_a[wl][j + 3];
            float a0 = head ? w0.y : w0.x;
            float a1 = head ? w1.y : w1.x;
            float a2 = head ? w2.y : w2.x;
            float a3 = head ? w3.y : w3.x;
            acc_bf16(acc, a0, &g_hb[i0 * HC + f]);
            acc_bf16(acc, a1, &g_hb[i1 * HC + f]);
            acc_bf16(acc, a2, &g_hb[i2 * HC + f]);
            acc_bf16(acc, a3, &g_hb[i3 * HC + f]);
        }
        for (; j < deg; j++) {
            int    sj = sh_s[wl][j];
            float2 wj = sh_a[wl][j];
            float  aj = head ? wj.y : wj.x;
            acc_bf16(acc, aj, &g_hb[sj * HC + f]);
        }
    } else {
        float m0 = -INFINITY, m1 = -INFINITY;
        for (int j = beg + lane; j < end; j += 32) {
            int s = g_col[j];
            float2 as = *(const float2*)&g_as[s * 2];
            float e0 = lrelu(as.x + ad.x);
            float e1 = lrelu(as.y + ad.y);
            *(float2*)&g_e[j * 2] = make_float2(e0, e1);
            m0 = fmaxf(m0, e0); m1 = fmaxf(m1, e1);
        }
#pragma unroll
        for (int o = 16; o; o >>= 1) {
            m0 = fmaxf(m0, __shfl_xor_sync(0xFFFFFFFFu, m0, o));
            m1 = fmaxf(m1, __shfl_xor_sync(0xFFFFFFFFu, m1, o));
        }
        float s0 = 0.f, s1 = 0.f;
        for (int j = beg + lane; j < end; j += 32) {
            float2 e = *(const float2*)&g_e[j * 2];
            float x0 = __expf(e.x - m0);
            float x1 = __expf(e.y - m1);
            *(float2*)&g_e[j * 2] = make_float2(x0, x1);
            s0 += x0; s1 += x1;
        }
#pragma unroll
        for (int o = 16; o; o >>= 1) {
            s0 += __shfl_xor_sync(0xFFFFFFFFu, s0, o);
            s1 += __shfl_xor_sync(0xFFFFFFFFu, s1, o);
        }
        float inv = head ? 1.f / (s1 + 1e-16f) : 1.f / (s0 + 1e-16f);
        __syncwarp();
        for (int j = beg; j < end; j++) {
            int s = g_col[j];
            float a = g_e[j * 2 + head] * inv;
            acc_bf16(acc, a, &g_hb[s * HC + f]);
        }
    }

    float2 bb0 = *(const float2*)&b[f];
    float2 bb1 = *(const float2*)&b[f + 2];
    float r0 = fmaxf(acc.x + bb0.x, 0.f);
    float r1 = fmaxf(acc.y + bb0.y, 0.f);
    float r2 = fmaxf(acc.z + bb1.x, 0.f);
    float r3 = fmaxf(acc.w + bb1.y, 0.f);
    uint2 packed;
    *(__nv_bfloat162*)&packed.x = __floats2bfloat162_rn(r0, r1);
    *(__nv_bfloat162*)&packed.y = __floats2bfloat162_rn(r2, r3);
    *(uint2*)&g_inb[w * HC + f] = packed;
}

// ---------------- fused pool + MLP head ----------------
__global__ void __launch_bounds__(256) k_head(
        const float* __restrict__ w1, const float* __restrict__ b1,
        const float* __restrict__ w2, const float* __restrict__ b2,
        const float* __restrict__ w3, const float* __restrict__ b3,
        float* __restrict__ out) {
    __shared__ float pool[HC];
    __shared__ float r1[L1S];
    __shared__ float r2[L2S];
    int g = blockIdx.x, tid = threadIdx.x;
    int beg = g_gstart[g], end = g_gstart[g + 1];

    if (tid < HC) {
        float sum = 0.f;
        for (int n = beg; n < end; n++)
            sum += __bfloat162float(g_inb[n * HC + tid]);
        pool[tid] = sum / fmaxf((float)(end - beg), 1.f);
    }
    __syncthreads();

    {
        float acc = 0.f;
#pragma unroll 4
        for (int k = 0; k < HC; k++) acc += pool[k] * w1[k * L1S + tid];
        acc += b1[tid];
        r1[tid] = acc > 0.f ? acc : 0.f;
    }
    __syncthreads();

    if (tid < L2S) {
        float acc = 0.f;
#pragma unroll 4
        for (int k = 0; k < L1S; k++) acc += r1[k] * w2[k * L2S + tid];
        acc += b2[tid];
        r2[tid] = acc > 0.f ? acc : 0.f;
    }
    __syncthreads();

    if (tid < OUTS) {
        float acc = 0.f;
#pragma unroll 4
        for (int k = 0; k < L2S; k++) acc += r2[k] * w3[k * OUTS + tid];
        out[g * OUTS + tid] = acc + b3[tid];
    }
}

// ---------------- host orchestration ----------------
extern "C" void kernel_launch(void* const* d_in, const int* in_sizes, int n_in,
                              void* d_out, int out_size) {
    const float* x       = (const float*)d_in[0];
    const void*  edge    = d_in[1];
    const void*  batch   = d_in[2];
    const float* W[3]    = {(const float*)d_in[3], (const float*)d_in[7],  (const float*)d_in[11]};
    const float* asrc[3] = {(const float*)d_in[4], (const float*)d_in[8],  (const float*)d_in[12]};
    const float* adst[3] = {(const float*)d_in[5], (const float*)d_in[9],  (const float*)d_in[13]};
    const float* bias[3] = {(const float*)d_in[6], (const float*)d_in[10], (const float*)d_in[14]};
    const float* lin1_w = (const float*)d_in[15];
    const float* lin1_b = (const float*)d_in[16];
    const float* lin2_w = (const float*)d_in[17];
    const float* lin2_b = (const float*)d_in[18];
    const float* out_w  = (const float*)d_in[19];
    const float* out_b  = (const float*)d_in[20];
    float* out = (float*)d_out;

    const int edge_blocks  = (EP + 255) / 256;
    const int gemm_blocks  = (NN + 127) / 128;
    const int warp8_blocks = (NN + 7) / 8;

    k_detect<<<1, 256>>>(edge);
    k_prep<<<(NN + 256) / 256, 256>>>(batch);
    k_deg<<<edge_blocks, 256>>>(edge);
    k_scanA<<<NB, 1024>>>();
    k_scanC<<<NB, 1024>>>();
    k_scatter<<<edge_blocks, 256>>>(edge);

    for (int l = 0; l < 3; l++) {
        k_gemm<<<gemm_blocks, 256>>>(x, W[l], asrc[l], adst[l], l == 0 ? 1 : 0);
        k_node<<<warp8_blocks, 256>>>(bias[l]);
    }

    k_head<<<GG, 256>>>(lin1_w, lin1_b, lin2_w, lin2_b, out_w, out_b, out);
}

// round 17
// speedup vs baseline: 1.1201x; 1.0162x over previous
#include <cuda_runtime.h>
#include <cuda_bf16.h>
#include <math.h>

// ---------------- problem constants ----------------
#define NN   50000
#define EE   800000
#define EP   (EE + NN)      // 850000
#define HH   2
#define HC   128
#define GG   128
#define L1S  256
#define L2S  128
#define OUTS 10
#define NEG_SLOPE 0.2f
#define NB   49             // scan blocks: 49*1024 >= NN

// ---------------- static device scratch ----------------
__device__ int   g_is64;
__device__ int   g_deg[NN];
__device__ int   g_fill[NN];
__device__ int   g_ptr[NN + 1];
__device__ int   g_col[EP];
__device__ int   g_bsum[NB];
__device__ int   g_gstart[GG + 1];
__device__ __nv_bfloat16 g_inb[NN * HC];  // layer activations (bf16)
__device__ __nv_bfloat16 g_hb [NN * HC];  // h (bf16, gather payload)
__device__ float g_as  [NN * HH];
__device__ float g_ad  [NN * HH];
__device__ float g_e   [EP * HH];         // deg>32 fallback only

__device__ __forceinline__ float lrelu(float v) {
    return v > 0.f ? v : NEG_SLOPE * v;
}

__device__ __forceinline__ int load_idx(const void* p, long long i, int is64) {
    return is64 ? (int)((const long long*)p)[i] : ((const int*)p)[i];
}

__device__ __forceinline__ unsigned f2tf32(float x) {
    unsigned r;
    asm("cvt.rna.tf32.f32 %0, %1;" : "=r"(r) : "f"(x));
    return r;
}

__device__ __forceinline__ void mma_tf32(float* d,
                                         const unsigned* a,
                                         const unsigned* b) {
    asm volatile(
        "mma.sync.aligned.m16n8k8.row.col.f32.tf32.tf32.f32 "
        "{%0,%1,%2,%3}, {%4,%5,%6,%7}, {%8,%9}, {%0,%1,%2,%3};\n"
        : "+f"(d[0]), "+f"(d[1]), "+f"(d[2]), "+f"(d[3])
        : "r"(a[0]), "r"(a[1]), "r"(a[2]), "r"(a[3]),
          "r"(b[0]), "r"(b[1]));
}

// accumulate a * (4 bf16 packed at p)
__device__ __forceinline__ void acc_bf16(float4& acc, float a, const __nv_bfloat16* p) {
    uint2 raw = *(const uint2*)p;
    __nv_bfloat162 p0 = *reinterpret_cast<__nv_bfloat162*>(&raw.x);
    __nv_bfloat162 p1 = *reinterpret_cast<__nv_bfloat162*>(&raw.y);
    float2 f0 = __bfloat1622float2(p0);
    float2 f1 = __bfloat1622float2(p1);
    acc.x += a * f0.x; acc.y += a * f0.y;
    acc.z += a * f1.x; acc.w += a * f1.y;
}

// ---------------- dtype sniffing + deg zero (one block) ----------------
__global__ void k_detect(const void* edge) {
    __shared__ int any_hi;
    int tid = threadIdx.x;                  // 256 threads
    if (tid == 0) any_hi = 0;
    __syncthreads();
    const unsigned long long* q = (const unsigned long long*)edge;
    int bad = 0;
    for (int i = tid; i < 1024; i += 256)
        if (q[i] >> 32) bad = 1;
    if (bad) any_hi = 1;
    // zero degree histogram (coalesced, vectorized)
    for (int i = tid; i < NN / 4; i += 256)
        ((int4*)g_deg)[i] = make_int4(0, 0, 0, 0);
    __syncthreads();
    if (tid == 0) g_is64 = any_hi ? 0 : 1;
}

// ---------------- degree histogram + graph boundaries (merged) -----------
__global__ void k_deg(const void* edge, const void* batch) {
    int i = blockIdx.x * blockDim.x + threadIdx.x;
    int is64 = g_is64;
    // graph boundaries (threads 0..NN)
    if (i <= NN) {
        if (i == 0) {
            int b0 = load_idx(batch, 0, is64);
            for (int g = 0; g <= b0; g++) g_gstart[g] = 0;
        } else {
            int bp = load_idx(batch, i - 1, is64);
            if (i == NN) {
                for (int g = bp + 1; g <= GG; g++) g_gstart[g] = NN;
            } else {
                int b = load_idx(batch, i, is64);
                if (b != bp)
                    for (int g = bp + 1; g <= b; g++) g_gstart[g] = i;
            }
        }
    }
    // degree histogram (threads 0..EP)
    if (i >= EP) return;
    int d;
    if (i < EE) d = load_idx(edge, (long long)EE + i, is64);
    else        d = i - EE;
    atomicAdd(&g_deg[d], 1);
}

// ---------------- multi-block exclusive scan (2 phases) ----------
__global__ void __launch_bounds__(1024) k_scanA() {
    __shared__ int wsum[32];
    int i = blockIdx.x * 1024 + threadIdx.x;
    int lane = threadIdx.x & 31, wid = threadIdx.x >> 5;
    int v = (i < NN) ? g_deg[i] : 0;
    int inc = v;
#pragma unroll
    for (int o = 1; o < 32; o <<= 1) {
        int t = __shfl_up_sync(0xFFFFFFFFu, inc, o);
        if (lane >= o) inc += t;
    }
    if (lane == 31) wsum[wid] = inc;
    __syncthreads();
    if (wid == 0) {
        int wv = wsum[lane];
        int winc = wv;
#pragma unroll
        for (int o = 1; o < 32; o <<= 1) {
            int t = __shfl_up_sync(0xFFFFFFFFu, winc, o);
            if (lane >= o) winc += t;
        }
        wsum[lane] = winc - wv;
        if (lane == 31) g_bsum[blockIdx.x] = winc;
    }
    __syncthreads();
    int ex = inc - v + wsum[wid];
    if (i < NN) g_ptr[i] = ex;
}

// scanC folds the block-partial scan (thread 0 serial over 49 partials)
__global__ void __launch_bounds__(1024) k_scanC() {
    __shared__ int s[NB];
    __shared__ int boff;
    if (threadIdx.x < NB) s[threadIdx.x] = g_bsum[threadIdx.x];
    __syncthreads();
    if (threadIdx.x == 0) {
        int off = 0;
        for (int k = 0; k < blockIdx.x; k++) off += s[k];
        boff = off;
        if (blockIdx.x == NB - 1) {
            int tot = off;
            for (int k = blockIdx.x; k < NB; k++) tot += s[k];
            g_ptr[NN] = tot;
        }
    }
    __syncthreads();
    int i = blockIdx.x * 1024 + threadIdx.x;
    if (i >= NN) return;
    g_ptr[i] += boff;
    g_fill[i] = 0;
}

// ---------------- scatter into CSR ----------------
__global__ void k_scatter(const void* edge) {
    int i = blockIdx.x * blockDim.x + threadIdx.x;
    if (i >= EP) return;
    int s, d;
    if (i < EE) {
        int is64 = g_is64;
        s = load_idx(edge, i, is64);
        d = load_idx(edge, (long long)EE + i, is64);
    } else {
        s = i - EE; d = s;
    }
    int pos = atomicAdd(&g_fill[d], 1);
    g_col[g_ptr[d] + pos] = s;
}

// ---------------- tf32 tensor-core GEMM + fused alpha ---------------------
// A source: layer0 = x (fp32), layers 1-2 = g_inb (bf16, exact->tf32 shift).
#define AS_STRIDE 36
#define BS_STRIDE 136
__global__ void __launch_bounds__(256) k_gemm(const float* __restrict__ A,
                                              const float* __restrict__ W,
                                              const float* __restrict__ a_src,
                                              const float* __restrict__ a_dst,
                                              int use_x) {
    __shared__ unsigned As[128 * AS_STRIDE];
    __shared__ unsigned Bs[32 * BS_STRIDE];
    __shared__ float s_as[128][2];
    __shared__ float s_ad[128][2];

    int row0 = blockIdx.x * 128;
    int tid = threadIdx.x;
    int wid = tid >> 5, lane = tid & 31;
    int g = lane >> 2, t = lane & 3;
    int wr = wid >> 2, wc = wid & 3;
    int head = wc >> 1;

    if (tid < 128) { s_as[tid][0] = 0.f; s_as[tid][1] = 0.f;
                     s_ad[tid][0] = 0.f; s_ad[tid][1] = 0.f; }

    float acc[4][4][4];
#pragma unroll
    for (int mf = 0; mf < 4; mf++)
#pragma unroll
        for (int nf = 0; nf < 4; nf++)
#pragma unroll
            for (int c = 0; c < 4; c++) acc[mf][nf][c] = 0.f;

    for (int k0 = 0; k0 < 128; k0 += 32) {
        if (use_x) {
#pragma unroll
            for (int l = 0; l < 4; l++) {
                int idx = tid + l * 256;
                int row = idx >> 3;
                int k4 = (idx & 7) << 2;
                int grow = row0 + row;
                float4 v = (grow < NN) ? *(const float4*)&A[grow * HC + k0 + k4]
                                       : make_float4(0.f, 0.f, 0.f, 0.f);
                unsigned* p = &As[row * AS_STRIDE + k4];
                p[0] = f2tf32(v.x); p[1] = f2tf32(v.y);
                p[2] = f2tf32(v.z); p[3] = f2tf32(v.w);
            }
        } else {
#pragma unroll
            for (int l = 0; l < 4; l++) {
                int idx = tid + l * 256;
                int row = idx >> 3;
                int k4 = (idx & 7) << 2;
                int grow = row0 + row;
                uint2 r = (grow < NN)
                    ? *(const uint2*)&g_inb[grow * HC + k0 + k4]
                    : make_uint2(0u, 0u);
                unsigned* p = &As[row * AS_STRIDE + k4];
                p[0] = r.x << 16; p[1] = r.x & 0xFFFF0000u;   // bf16 -> tf32 exact
                p[2] = r.y << 16; p[3] = r.y & 0xFFFF0000u;
            }
        }
#pragma unroll
        for (int l = 0; l < 4; l++) {
            int idx = tid + l * 256;
            int k = idx >> 5;
            int n4 = (idx & 31) << 2;
            float4 v = *(const float4*)&W[(k0 + k) * HC + n4];
            unsigned* p = &Bs[k * BS_STRIDE + n4];
            p[0] = f2tf32(v.x); p[1] = f2tf32(v.y);
            p[2] = f2tf32(v.z); p[3] = f2tf32(v.w);
        }
        __syncthreads();

#pragma unroll
        for (int kk = 0; kk < 32; kk += 8) {
            unsigned af[4][4];
#pragma unroll
            for (int mf = 0; mf < 4; mf++) {
                int r = wr * 64 + mf * 16 + g;
                af[mf][0] = As[r * AS_STRIDE + kk + t];
                af[mf][1] = As[(r + 8) * AS_STRIDE + kk + t];
                af[mf][2] = As[r * AS_STRIDE + kk + t + 4];
                af[mf][3] = As[(r + 8) * AS_STRIDE + kk + t + 4];
            }
            unsigned bf[4][2];
#pragma unroll
            for (int nf = 0; nf < 4; nf++) {
                int n = wc * 32 + nf * 8 + g;
                bf[nf][0] = Bs[(kk + t) * BS_STRIDE + n];
                bf[nf][1] = Bs[(kk + t + 4) * BS_STRIDE + n];
            }
#pragma unroll
            for (int mf = 0; mf < 4; mf++)
#pragma unroll
                for (int nf = 0; nf < 4; nf++)
                    mma_tf32(acc[mf][nf], af[mf], bf[nf]);
        }
        __syncthreads();
    }

    float asv[8], adv[8];
#pragma unroll
    for (int nf = 0; nf < 4; nf++) {
#pragma unroll
        for (int c = 0; c < 2; c++) {
            int col = wc * 32 + nf * 8 + 2 * t + c;
            asv[nf * 2 + c] = a_src[col];
            adv[nf * 2 + c] = a_dst[col];
        }
    }

#pragma unroll
    for (int mf = 0; mf < 4; mf++) {
#pragma unroll
        for (int r = 0; r < 2; r++) {
            int rloc = wr * 64 + mf * 16 + g + 8 * r;
            int grow = row0 + rloc;
            float ps = 0.f, pd = 0.f;
#pragma unroll
            for (int nf = 0; nf < 4; nf++) {
                float v0 = acc[mf][nf][2 * r];
                float v1 = acc[mf][nf][2 * r + 1];
                ps += v0 * asv[nf * 2] + v1 * asv[nf * 2 + 1];
                pd += v0 * adv[nf * 2] + v1 * adv[nf * 2 + 1];
                if (grow < NN) {
                    int col = wc * 32 + nf * 8 + 2 * t;
                    *(__nv_bfloat162*)&g_hb[grow * HC + col] =
                        __floats2bfloat162_rn(v0, v1);
                }
            }
            ps += __shfl_xor_sync(0xFFFFFFFFu, ps, 1);
            ps += __shfl_xor_sync(0xFFFFFFFFu, ps, 2);
            pd += __shfl_xor_sync(0xFFFFFFFFu, pd, 1);
            pd += __shfl_xor_sync(0xFFFFFFFFu, pd, 2);
            if (t == 0) {
                atomicAdd(&s_as[rloc][head], ps);
                atomicAdd(&s_ad[rloc][head], pd);
            }
        }
    }
    __syncthreads();

    if (tid < 128) {
        int grow = row0 + tid;
        if (grow < NN) {
            *(float2*)&g_as[grow * 2] = make_float2(s_as[tid][0], s_as[tid][1]);
            *(float2*)&g_ad[grow * 2] = make_float2(s_ad[tid][0], s_ad[tid][1]);
        }
    }
}

// ---------------- fused softmax + aggregation: warp per dst node ---------
__global__ void __launch_bounds__(256) k_node(const float* __restrict__ b) {
    __shared__ int    sh_s[8][32];
    __shared__ float2 sh_a[8][32];
    int w = (blockIdx.x * blockDim.x + threadIdx.x) >> 5;
    if (w >= NN) return;
    int lane = threadIdx.x & 31;
    int wl = (threadIdx.x >> 5);
    int beg = g_ptr[w], end = g_ptr[w + 1];
    int deg = end - beg;
    float2 ad = *(const float2*)&g_ad[w * 2];

    int f = lane * 4;
    int head = f >> 6;
    float4 acc = make_float4(0.f, 0.f, 0.f, 0.f);

    if (deg <= 32) {
        int s = 0;
        float e0 = -INFINITY, e1 = -INFINITY;
        if (lane < deg) {
            s = g_col[beg + lane];
            float2 as = *(const float2*)&g_as[s * 2];
            e0 = lrelu(as.x + ad.x);
            e1 = lrelu(as.y + ad.y);
        }
        float m0 = e0, m1 = e1;
#pragma unroll
        for (int o = 16; o; o >>= 1) {
            m0 = fmaxf(m0, __shfl_xor_sync(0xFFFFFFFFu, m0, o));
            m1 = fmaxf(m1, __shfl_xor_sync(0xFFFFFFFFu, m1, o));
        }
        float x0 = (lane < deg) ? __expf(e0 - m0) : 0.f;
        float x1 = (lane < deg) ? __expf(e1 - m1) : 0.f;
        float s0 = x0, s1 = x1;
#pragma unroll
        for (int o = 16; o; o >>= 1) {
            s0 += __shfl_xor_sync(0xFFFFFFFFu, s0, o);
            s1 += __shfl_xor_sync(0xFFFFFFFFu, s1, o);
        }
        sh_s[wl][lane] = s;
        sh_a[wl][lane] = make_float2(x0 / (s0 + 1e-16f), x1 / (s1 + 1e-16f));
        __syncwarp();

        // gather: 8 independent uint2 loads per round
        int j = 0;
        for (; j + 7 < deg; j += 8) {
#pragma unroll
            for (int k = 0; k < 8; k += 4) {
                int    i0 = sh_s[wl][j + k],     i1 = sh_s[wl][j + k + 1];
                int    i2 = sh_s[wl][j + k + 2], i3 = sh_s[wl][j + k + 3];
                float2 w0 = sh_a[wl][j + k],     w1 = sh_a[wl][j + k + 1];
                float2 w2 = sh_a[wl][j + k + 2], w3 = sh_a[wl][j + k + 3];
                float a0 = head ? w0.y : w0.x;
                float a1 = head ? w1.y : w1.x;
                float a2 = head ? w2.y : w2.x;
                float a3 = head ? w3.y : w3.x;
                acc_bf16(acc, a0, &g_hb[i0 * HC + f]);
                acc_bf16(acc, a1, &g_hb[i1 * HC + f]);
                acc_bf16(acc, a2, &g_hb[i2 * HC + f]);
                acc_bf16(acc, a3, &g_hb[i3 * HC + f]);
            }
        }
        for (; j + 3 < deg; j += 4) {
            int    i0 = sh_s[wl][j],     i1 = sh_s[wl][j + 1];
            int    i2 = sh_s[wl][j + 2], i3 = sh_s[wl][j + 3];
            float2 w0 = sh_a[wl][j],     w1 = sh_a[wl][j + 1];
            float2 w2 = sh_a[wl][j + 2], w3 = sh_a[wl][j + 3];
            float a0 = head ? w0.y : w0.x;
            float a1 = head ? w1.y : w1.x;
            float a2 = head ? w2.y : w2.x;
            float a3 = head ? w3.y : w3.x;
            acc_bf16(acc, a0, &g_hb[i0 * HC + f]);
            acc_bf16(acc, a1, &g_hb[i1 * HC + f]);
            acc_bf16(acc, a2, &g_hb[i2 * HC + f]);
            acc_bf16(acc, a3, &g_hb[i3 * HC + f]);
        }
        for (; j < deg; j++) {
            int    sj = sh_s[wl][j];
            float2 wj = sh_a[wl][j];
            float  aj = head ? wj.y : wj.x;
            acc_bf16(acc, aj, &g_hb[sj * HC + f]);
        }
    } else {
        float m0 = -INFINITY, m1 = -INFINITY;
        for (int j = beg + lane; j < end; j += 32) {
            int s = g_col[j];
            float2 as = *(const float2*)&g_as[s * 2];
            float e0 = lrelu(as.x + ad.x);
            float e1 = lrelu(as.y + ad.y);
            *(float2*)&g_e[j * 2] = make_float2(e0, e1);
            m0 = fmaxf(m0, e0); m1 = fmaxf(m1, e1);
        }
#pragma unroll
        for (int o = 16; o; o >>= 1) {
            m0 = fmaxf(m0, __shfl_xor_sync(0xFFFFFFFFu, m0, o));
            m1 = fmaxf(m1, __shfl_xor_sync(0xFFFFFFFFu, m1, o));
        }
        float s0 = 0.f, s1 = 0.f;
        for (int j = beg + lane; j < end; j += 32) {
            float2 e = *(const float2*)&g_e[j * 2];
            float x0 = __expf(e.x - m0);
            float x1 = __expf(e.y - m1);
            *(float2*)&g_e[j * 2] = make_float2(x0, x1);
            s0 += x0; s1 += x1;
        }
#pragma unroll
        for (int o = 16; o; o >>= 1) {
            s0 += __shfl_xor_sync(0xFFFFFFFFu, s0, o);
            s1 += __shfl_xor_sync(0xFFFFFFFFu, s1, o);
        }
        float inv = head ? 1.f / (s1 + 1e-16f) : 1.f / (s0 + 1e-16f);
        __syncwarp();
        for (int j = beg; j < end; j++) {
            int s = g_col[j];
            float a = g_e[j * 2 + head] * inv;
            acc_bf16(acc, a, &g_hb[s * HC + f]);
        }
    }

    float2 bb0 = *(const float2*)&b[f];
    float2 bb1 = *(const float2*)&b[f + 2];
    float r0 = fmaxf(acc.x + bb0.x, 0.f);
    float r1 = fmaxf(acc.y + bb0.y, 0.f);
    float r2 = fmaxf(acc.z + bb1.x, 0.f);
    float r3 = fmaxf(acc.w + bb1.y, 0.f);
    uint2 packed;
    *(__nv_bfloat162*)&packed.x = __floats2bfloat162_rn(r0, r1);
    *(__nv_bfloat162*)&packed.y = __floats2bfloat162_rn(r2, r3);
    *(uint2*)&g_inb[w * HC + f] = packed;
}

// ---------------- fused pool + MLP head ----------------
__global__ void __launch_bounds__(256) k_head(
        const float* __restrict__ w1, const float* __restrict__ b1,
        const float* __restrict__ w2, const float* __restrict__ b2,
        const float* __restrict__ w3, const float* __restrict__ b3,
        float* __restrict__ out) {
    __shared__ float pool[HC];
    __shared__ float r1[L1S];
    __shared__ float r2[L2S];
    int g = blockIdx.x, tid = threadIdx.x;
    int beg = g_gstart[g], end = g_gstart[g + 1];

    if (tid < HC) {
        float sum = 0.f;
        for (int n = beg; n < end; n++)
            sum += __bfloat162float(g_inb[n * HC + tid]);
        pool[tid] = sum / fmaxf((float)(end - beg), 1.f);
    }
    __syncthreads();

    {
        float acc = 0.f;
#pragma unroll 4
        for (int k = 0; k < HC; k++) acc += pool[k] * w1[k * L1S + tid];
        acc += b1[tid];
        r1[tid] = acc > 0.f ? acc : 0.f;
    }
    __syncthreads();

    if (tid < L2S) {
        float acc = 0.f;
#pragma unroll 4
        for (int k = 0; k < L1S; k++) acc += r1[k] * w2[k * L2S + tid];
        acc += b2[tid];
        r2[tid] = acc > 0.f ? acc : 0.f;
    }
    __syncthreads();

    if (tid < OUTS) {
        float acc = 0.f;
#pragma unroll 4
        for (int k = 0; k < L2S; k++) acc += r2[k] * w3[k * OUTS + tid];
        out[g * OUTS + tid] = acc + b3[tid];
    }
}

// ---------------- host orchestration ----------------
extern "C" void kernel_launch(void* const* d_in, const int* in_sizes, int n_in,
                              void* d_out, int out_size) {
    const float* x       = (const float*)d_in[0];
    const void*  edge    = d_in[1];
    const void*  batch   = d_in[2];
    const float* W[3]    = {(const float*)d_in[3], (const float*)d_in[7],  (const float*)d_in[11]};
    const float* asrc[3] = {(const float*)d_in[4], (const float*)d_in[8],  (const float*)d_in[12]};
    const float* adst[3] = {(const float*)d_in[5], (const float*)d_in[9],  (const float*)d_in[13]};
    const float* bias[3] = {(const float*)d_in[6], (const float*)d_in[10], (const float*)d_in[14]};
    const float* lin1_w = (const float*)d_in[15];
    const float* lin1_b = (const float*)d_in[16];
    const float* lin2_w = (const float*)d_in[17];
    const float* lin2_b = (const float*)d_in[18];
    const float* out_w  = (const float*)d_in[19];
    const float* out_b  = (const float*)d_in[20];
    float* out = (float*)d_out;

    const int edge_blocks  = (EP + 255) / 256;
    const int gemm_blocks  = (NN + 127) / 128;
    const int warp8_blocks = (NN + 7) / 8;

    k_detect<<<1, 256>>>(edge);                       // detect + zero deg
    k_deg<<<edge_blocks, 256>>>(edge, batch);         // histogram + gstart
    k_scanA<<<NB, 1024>>>();
    k_scanC<<<NB, 1024>>>();
    k_scatter<<<edge_blocks, 256>>>(edge);

    for (int l = 0; l < 3; l++) {
        k_gemm<<<gemm_blocks, 256>>>(x, W[l], asrc[l], adst[l], l == 0 ? 1 : 0);
        k_node<<<warp8_blocks, 256>>>(bias[l]);
    }

    k_head<<<GG, 256>>>(lin1_w, lin1_b, lin2_w, lin2_b, out_w, out_b, out);
}